// round 11
// baseline (speedup 1.0000x reference)
#include <cuda_runtime.h>
#include <cfloat>
#include <stdint.h>
#include <math.h>

// ---------------------------------------------------------------------------
// FocalLoss (RetinaNet) fully-fused single-kernel for GB300, v10.
//   v9 math (lg2-domain focal, cancelled cross-multiply argmax) plus:
//   - ILP-2: each thread processes TWO anchors; the 32-iteration IoU loop
//     shares every shared-memory load between them and interleaves two
//     independent FSETP/FSEL dependency chains (covers issue-idle cycles)
//   - sarea loaded as float4 (1 LDS per 4 GTs instead of 4)
//   - last-block-done finalize + accumulator reset (single launch)
// ---------------------------------------------------------------------------

#define TPB 256
#define M_MAX 64
#define B_MAX 32
#define LN2F 0.69314718055994530942f

__device__ double g_cs[B_MAX];
__device__ double g_rs[B_MAX];
__device__ int    g_np[B_MAX];
__device__ int    g_arrive = 0;

__device__ __forceinline__ float fsqrt_ap(float x) {
    float r; asm("sqrt.approx.f32 %0, %1;" : "=f"(r) : "f"(x)); return r;
}

// Per-anchor epilogue: focal classification + smooth-L1 regression.
template <int CT>
__device__ __forceinline__ void anchor_loss(
    const float* __restrict__ cp,       // this anchor's cls row (clamped)
    const float4* __restrict__ reg4,    // reg rows base [b*A]
    int aidx,                           // clamped anchor index within image
    const float4 ab, float aw, float ah,
    const float4* sbox, const int* slbl,
    float binter, float bS, int arg, bool valid, int C,
    float& cls_sum, float& reg_sum, int& pos_cnt)
{
    const float best = binter / (bS - binter);     // one precise division
    const bool  pos     = (best >= 0.5f) && valid;
    const bool  contrib = (pos || best < 0.4f) && valid;

    // branch-free negative focal term: s = sum p*sqrt(p)*lg2(1-p)
    float s = 0.0f;
    if (CT == 20) {
        const float4* cp4 = (const float4*)cp;
        #pragma unroll
        for (int i = 0; i < 5; i++) {
            const float4 v = cp4[i];
            float p;
            p = v.x; s = fmaf(p * fsqrt_ap(p), __log2f(1.0f - p), s);
            p = v.y; s = fmaf(p * fsqrt_ap(p), __log2f(1.0f - p), s);
            p = v.z; s = fmaf(p * fsqrt_ap(p), __log2f(1.0f - p), s);
            p = v.w; s = fmaf(p * fsqrt_ap(p), __log2f(1.0f - p), s);
        }
    } else {
        for (int c = 0; c < C; c++) {
            const float p = fminf(fmaxf(cp[c], 1e-8f), 1.0f - 1e-8f);
            s = fmaf(p * fsqrt_ap(p), __log2f(1.0f - p), s);
        }
    }
    float ca = contrib ? (-0.8f * LN2F) * s : 0.0f;

    if (pos) {
        pos_cnt++;
        const int lbl = slbl[arg];
        const float pl = cp[lbl];                   // L1-hot reload
        const float ql = 1.0f - pl;
        const float base = s - pl * fsqrt_ap(pl) * __log2f(ql);
        const float post = ql * fsqrt_ap(ql) * __log2f(pl);
        ca = -LN2F * fmaf(0.8f, base, 0.2f * post);

        const float4 gb = sbox[arg];
        const float gwr = gb.z - gb.x, ghr = gb.w - gb.y;
        const float gcx = gb.x + 0.5f * gwr;
        const float gcy = gb.y + 0.5f * ghr;
        const float gw  = fmaxf(gwr, 1.0f);
        const float gh  = fmaxf(ghr, 1.0f);
        const float acx = ab.x + 0.5f * aw;
        const float acy = ab.y + 0.5f * ah;

        const float t0 = ((gcx - acx) / aw) / 0.1f;
        const float t1 = ((gcy - acy) / ah) / 0.1f;
        const float t2 = logf(gw / aw) / 0.2f;
        const float t3 = logf(gh / ah) / 0.2f;

        const float4 rg = reg4[aidx];

        const float thr = 1.0f / 9.0f;
        const float off = 0.5f / 9.0f;
        float sr = 0.0f, d;
        d = fabsf(t0 - rg.x); sr += (d <= thr) ? 4.5f * d * d : d - off;
        d = fabsf(t1 - rg.y); sr += (d <= thr) ? 4.5f * d * d : d - off;
        d = fabsf(t2 - rg.z); sr += (d <= thr) ? 4.5f * d * d : d - off;
        d = fabsf(t3 - rg.w); sr += (d <= thr) ? 4.5f * d * d : d - off;
        reg_sum += sr;
    }
    cls_sum += ca;
}

template <int MT, int CT>
__global__ void __launch_bounds__(TPB, 4)
fl_kernel(const float* __restrict__ cls,
          const float* __restrict__ reg,
          const float* __restrict__ anc,
          const float* __restrict__ ann,
          float* __restrict__ out,
          int A, int C, int M, int B, int nblocks)
{
    __shared__ float4 sbox[M_MAX];                       // (x1,y1,x2,y2)
    __shared__ __align__(16) float sarea[M_MAX];
    __shared__ int    slbl[M_MAX];
    __shared__ bool   s_last;

    const int b   = blockIdx.y;
    const int tid = threadIdx.x;
    const int MM  = MT ? MT : M;
    const unsigned FULL = 0xFFFFFFFFu;

    // ---- load GT boxes (invalid -> degenerate zero box, never selected) ----
    if (tid < MM) {
        const float* g = ann + ((size_t)b * MM + tid) * 5;
        float x1 = g[0], y1 = g[1], x2 = g[2], y2 = g[3];
        const float l = g[4];
        if (l == -1.0f) { x1 = 0.f; y1 = 0.f; x2 = 0.f; y2 = 0.f; }
        sbox[tid]  = make_float4(x1, y1, x2, y2);
        sarea[tid] = (x2 - x1) * (y2 - y1);
        slbl[tid]  = (int)l;
    }
    __syncthreads();

    // ---- two anchors per thread ----
    const int a0 = blockIdx.x * (2 * TPB) + tid;
    const int a1 = a0 + TPB;
    const bool v0 = (a0 < A);
    const bool v1 = (a1 < A);
    const int i0 = v0 ? a0 : 0;          // clamped indices for safe loads
    const int i1 = v1 ? a1 : 0;

    const float4* anc4 = (const float4*)anc;
    const float4 ab0 = anc4[i0];
    const float4 ab1 = anc4[i1];
    const float aw0 = ab0.z - ab0.x, ah0 = ab0.w - ab0.y;
    const float aw1 = ab1.z - ab1.x, ah1 = ab1.w - ab1.y;
    const float area0 = aw0 * ah0;
    const float area1 = aw1 * ah1;

    // --- fused IoU argmax for both anchors; smem loads shared ---
    float bi0 = 0.0f, bs0 = 1.0f;  int arg0 = 0;
    float bi1 = 0.0f, bs1 = 1.0f;  int arg1 = 0;

    if (MT == 32) {
        const float4* sarea4 = (const float4*)sarea;
        #pragma unroll
        for (int mo = 0; mo < 8; mo++) {
            const float4 sv = sarea4[mo];
            #pragma unroll
            for (int mi = 0; mi < 4; mi++) {
                const int m = mo * 4 + mi;
                const float4 g = sbox[m];
                const float sa = (mi == 0) ? sv.x : (mi == 1) ? sv.y
                               : (mi == 2) ? sv.z : sv.w;
                {
                    const float iw = fminf(ab0.z, g.z) - fmaxf(ab0.x, g.x);
                    const float ih = fminf(ab0.w, g.w) - fmaxf(ab0.y, g.y);
                    const float inter = fmaxf(iw, 0.0f) * fmaxf(ih, 0.0f);
                    const float S = area0 + sa;
                    if (inter * bs0 > bi0 * S) { bi0 = inter; bs0 = S; arg0 = m; }
                }
                {
                    const float iw = fminf(ab1.z, g.z) - fmaxf(ab1.x, g.x);
                    const float ih = fminf(ab1.w, g.w) - fmaxf(ab1.y, g.y);
                    const float inter = fmaxf(iw, 0.0f) * fmaxf(ih, 0.0f);
                    const float S = area1 + sa;
                    if (inter * bs1 > bi1 * S) { bi1 = inter; bs1 = S; arg1 = m; }
                }
            }
        }
    } else {
        for (int m = 0; m < MM; m++) {
            const float4 g = sbox[m];
            const float sa = sarea[m];
            {
                const float iw = fminf(ab0.z, g.z) - fmaxf(ab0.x, g.x);
                const float ih = fminf(ab0.w, g.w) - fmaxf(ab0.y, g.y);
                const float inter = fmaxf(iw, 0.0f) * fmaxf(ih, 0.0f);
                const float S = area0 + sa;
                if (inter * bs0 > bi0 * S) { bi0 = inter; bs0 = S; arg0 = m; }
            }
            {
                const float iw = fminf(ab1.z, g.z) - fmaxf(ab1.x, g.x);
                const float ih = fminf(ab1.w, g.w) - fmaxf(ab1.y, g.y);
                const float inter = fmaxf(iw, 0.0f) * fmaxf(ih, 0.0f);
                const float S = area1 + sa;
                if (inter * bs1 > bi1 * S) { bi1 = inter; bs1 = S; arg1 = m; }
            }
        }
    }

    // --- per-anchor epilogues (sequential: keeps register pressure low) ---
    float cls_acc = 0.0f, reg_acc = 0.0f;
    int   pos_i = 0;
    const int Ceff = CT ? CT : C;
    const float*  clsb = cls + (size_t)b * A * Ceff;
    const float4* reg4 = (const float4*)reg + (size_t)b * A;

    anchor_loss<CT>(clsb + (size_t)i0 * Ceff, reg4, i0, ab0, aw0, ah0,
                    sbox, slbl, bi0, bs0, arg0, v0, Ceff,
                    cls_acc, reg_acc, pos_i);
    anchor_loss<CT>(clsb + (size_t)i1 * Ceff, reg4, i1, ab1, aw1, ah1,
                    sbox, slbl, bi1, bs1, arg1, v1, Ceff,
                    cls_acc, reg_acc, pos_i);

    // ---- block reduction: warp shuffle/REDUX -> shared -> fp64 atomics ----
    #pragma unroll
    for (int o = 16; o > 0; o >>= 1) {
        cls_acc += __shfl_down_sync(FULL, cls_acc, o);
        reg_acc += __shfl_down_sync(FULL, reg_acc, o);
    }
    pos_i = __reduce_add_sync(FULL, (unsigned)pos_i);

    __shared__ float wc[TPB / 32], wr[TPB / 32];
    __shared__ int   wp[TPB / 32];
    const int wid = tid >> 5;
    const int lid = tid & 31;
    if (lid == 0) { wc[wid] = cls_acc; wr[wid] = reg_acc; wp[wid] = pos_i; }
    __syncthreads();

    if (tid < 32) {
        const int nwarp = TPB / 32;
        float csum = (lid < nwarp) ? wc[lid] : 0.0f;
        float rsum = (lid < nwarp) ? wr[lid] : 0.0f;
        int   psum = (lid < nwarp) ? wp[lid] : 0;
        #pragma unroll
        for (int o = 4; o > 0; o >>= 1) {
            csum += __shfl_down_sync(FULL, csum, o);
            rsum += __shfl_down_sync(FULL, rsum, o);
        }
        psum = __reduce_add_sync(FULL, (unsigned)psum);
        if (lid == 0) {
            if (csum != 0.0f) atomicAdd(&g_cs[b], (double)csum);
            if (rsum != 0.0f) atomicAdd(&g_rs[b], (double)rsum);
            if (psum != 0)    atomicAdd(&g_np[b], psum);
            __threadfence();
            const int prev = atomicAdd(&g_arrive, 1);
            s_last = (prev == nblocks - 1);
        }
    }
    __syncthreads();

    // ---- last block finalizes the output and resets the accumulators ----
    if (s_last && tid < 32) {
        float cl = 0.0f, rl = 0.0f;
        if (tid < B) {
            int nvv = 0;
            for (int m = 0; m < M; m++)
                nvv += (ann[((size_t)tid * M + m) * 5 + 4] != -1.0f) ? 1 : 0;
            const int np = g_np[tid];
            const float npf = (float)np;
            cl = (float)g_cs[tid] / fmaxf(npf, 1.0f);
            rl = (float)g_rs[tid] / fmaxf(4.0f * npf, 1.0f);
            if (np == 0) rl = 0.0f;
            if (nvv == 0) { cl = 0.0f; rl = 0.0f; }
        }
        #pragma unroll
        for (int o = 16; o > 0; o >>= 1) {
            cl += __shfl_down_sync(FULL, cl, o);
            rl += __shfl_down_sync(FULL, rl, o);
        }
        if (tid == 0) {
            out[0] = cl / (float)B;
            out[1] = rl / (float)B;
        }
        g_cs[tid] = 0.0;
        g_rs[tid] = 0.0;
        g_np[tid] = 0;
        if (tid == 0) g_arrive = 0;
    }
}

extern "C" void kernel_launch(void* const* d_in, const int* in_sizes, int n_in,
                              void* d_out, int out_size)
{
    const float* cls = (const float*)d_in[0];
    const float* reg = (const float*)d_in[1];
    const float* anc = (const float*)d_in[2];
    const float* ann = (const float*)d_in[3];
    float* out = (float*)d_out;

    const int A = in_sizes[2] / 4;            // anchors [1,A,4]
    const int B = in_sizes[1] / (A * 4);      // regressions [B,A,4]
    const int C = in_sizes[0] / (B * A);      // classifications [B,A,C]
    const int M = in_sizes[3] / (B * 5);      // annotations [B,M,5]

    dim3 block(TPB);
    dim3 grid((A + 2 * TPB - 1) / (2 * TPB), B);
    const int nblocks = grid.x * grid.y;

    if (M == 32 && C == 20)
        fl_kernel<32, 20><<<grid, block>>>(cls, reg, anc, ann, out, A, C, M, B, nblocks);
    else
        fl_kernel<0, 0><<<grid, block>>>(cls, reg, anc, ann, out, A, C, M, B, nblocks);
}